// round 1
// baseline (speedup 1.0000x reference)
#include <cuda_runtime.h>

// Problem constants
constexpr int Bc  = 2;
constexpr int Sc  = 2048;
constexpr int Dc  = 1024;
constexpr int Hc  = 16;
constexpr int DKc = 64;

// Scratch (device globals: allocation-free per harness rules)
__device__ float g_q[(size_t)Bc * Hc * Sc * DKc];   // [B,H,S,DK]
__device__ float g_k[(size_t)Bc * Hc * Sc * DKc];
__device__ float g_v[(size_t)Bc * Hc * Sc * DKc];
__device__ float g_att[(size_t)Bc * Sc * Dc];       // [B,S,D] (head-interleaved)

// ---------------------------------------------------------------------------
// Tiled GEMM: C[4096,1024] = A[4096,1024] @ W[1024,1024] + bias
// 64x64 tile, BK=16, 256 threads, 4x4 micro-tile per thread.
// TR=true scatters output into head-major [B,H,S,DK]; else row-major [M,D].
// ---------------------------------------------------------------------------
template <bool TR>
__device__ __forceinline__ void gemm_body(const float* __restrict__ A,
                                          const float* __restrict__ W,
                                          const float* __restrict__ bias,
                                          float* __restrict__ C) {
    __shared__ float As[16][64];   // [k][m]
    __shared__ float Ws[16][64];   // [k][n]

    const int tid = threadIdx.x;
    const int tx  = tid & 15;      // 16 threads across N
    const int ty  = tid >> 4;      // 16 threads across M
    const int m0  = blockIdx.y << 6;
    const int n0  = blockIdx.x << 6;

    // Load mappings
    const int arow = tid >> 2;            // 0..63
    const int akq  = (tid & 3) << 2;      // 0,4,8,12
    const int wrow = tid >> 4;            // 0..15
    const int wcol = (tid & 15) << 2;     // 0..60

    float acc[4][4];
#pragma unroll
    for (int i = 0; i < 4; i++)
#pragma unroll
        for (int j = 0; j < 4; j++) acc[i][j] = 0.0f;

    const float* Aptr = A + (size_t)(m0 + arow) * Dc + akq;
    const float* Wptr = W + (size_t)wrow * Dc + n0 + wcol;

    for (int k0 = 0; k0 < Dc; k0 += 16) {
        float4 av = *(const float4*)(Aptr + k0);
        As[akq + 0][arow] = av.x;
        As[akq + 1][arow] = av.y;
        As[akq + 2][arow] = av.z;
        As[akq + 3][arow] = av.w;
        *(float4*)&Ws[wrow][wcol] = *(const float4*)(Wptr + (size_t)k0 * Dc);
        __syncthreads();

#pragma unroll
        for (int kk = 0; kk < 16; kk++) {
            float4 a4 = *(const float4*)&As[kk][ty << 2];
            float4 b4 = *(const float4*)&Ws[kk][tx << 2];
            float a[4] = {a4.x, a4.y, a4.z, a4.w};
            float b[4] = {b4.x, b4.y, b4.z, b4.w};
#pragma unroll
            for (int i = 0; i < 4; i++)
#pragma unroll
                for (int j = 0; j < 4; j++) acc[i][j] += a[i] * b[j];
        }
        __syncthreads();
    }

#pragma unroll
    for (int i = 0; i < 4; i++) {
        const int m = m0 + (ty << 2) + i;
#pragma unroll
        for (int j = 0; j < 4; j++) {
            const int n   = n0 + (tx << 2) + j;
            const float val = acc[i][j] + bias[n];
            if (TR) {
                const int b  = m >> 11;          // m / S
                const int s  = m & (Sc - 1);     // m % S
                const int h  = n >> 6;           // n / DK
                const int dk = n & 63;           // n % DK
                C[(((size_t)b * Hc + h) * Sc + s) * DKc + dk] = val;
            } else {
                C[(size_t)m * Dc + n] = val;
            }
        }
    }
}

__global__ __launch_bounds__(256) void qkv_gemm_kernel(
    const float* __restrict__ q, const float* __restrict__ k, const float* __restrict__ v,
    const float* __restrict__ Wq, const float* __restrict__ bq,
    const float* __restrict__ Wk, const float* __restrict__ bk,
    const float* __restrict__ Wv, const float* __restrict__ bv) {
    const float* A;
    const float* W;
    const float* bias;
    float* C;
    if (blockIdx.z == 0)      { A = q; W = Wq; bias = bq; C = g_q; }
    else if (blockIdx.z == 1) { A = k; W = Wk; bias = bk; C = g_k; }
    else                      { A = v; W = Wv; bias = bv; C = g_v; }
    gemm_body<true>(A, W, bias, C);
}

__global__ __launch_bounds__(256) void out_gemm_kernel(
    const float* __restrict__ Wo, const float* __restrict__ bo,
    float* __restrict__ out) {
    gemm_body<false>(g_att, Wo, bo, out);
}

// ---------------------------------------------------------------------------
// Flash-style attention. Grid: (S/64, B*H). Block: 256 threads (8 warps).
// Warp w owns q-rows w*8..w*8+7 of a 64-row q tile. Each row is handled by a
// quarter-warp (4 lanes), each lane covering 16 of DK=64. Online softmax.
// ---------------------------------------------------------------------------
__global__ __launch_bounds__(256) void attn_kernel() {
    __shared__ float Ksh[64][64];
    __shared__ float Vsh[64][64];

    const int bh  = blockIdx.y;                 // 0..31 (b*H + h)
    const int qt  = blockIdx.x;                 // 0..31
    const int tid = threadIdx.x;
    const int w   = tid >> 5;
    const int l   = tid & 31;
    const int lr  = l >> 2;                     // local row in warp (0..7)
    const int qd  = (l & 3) << 4;               // dk offset: 0,16,32,48
    const int row = (qt << 6) + (w << 3) + lr;  // global q row in sequence

    // Q fragment in registers, pre-scaled by 1/sqrt(DK) = 0.125
    float qreg[16];
    {
        const float* Qp = g_q + ((size_t)bh * Sc + row) * DKc + qd;
#pragma unroll
        for (int i = 0; i < 16; i += 4) {
            float4 t = *(const float4*)(Qp + i);
            qreg[i + 0] = t.x * 0.125f;
            qreg[i + 1] = t.y * 0.125f;
            qreg[i + 2] = t.z * 0.125f;
            qreg[i + 3] = t.w * 0.125f;
        }
    }

    float mrun = -3.0e38f;
    float lsum = 0.0f;
    float acc[16];
#pragma unroll
    for (int i = 0; i < 16; i++) acc[i] = 0.0f;

    const float* Kb = g_k + (size_t)bh * Sc * DKc;
    const float* Vb = g_v + (size_t)bh * Sc * DKc;
    const int ldr = tid >> 2;            // 0..63
    const int ldc = (tid & 3) << 4;      // 0,16,32,48

    for (int kb = 0; kb < Sc; kb += 64) {
        __syncthreads();
#pragma unroll
        for (int i = 0; i < 16; i += 4) {
            *(float4*)&Ksh[ldr][ldc + i] = *(const float4*)&Kb[(size_t)(kb + ldr) * DKc + ldc + i];
            *(float4*)&Vsh[ldr][ldc + i] = *(const float4*)&Vb[(size_t)(kb + ldr) * DKc + ldc + i];
        }
        __syncthreads();

        // Scores: s[c] = (q/8) . K[c]  (partial over this lane's 16 dk)
        float s[64];
#pragma unroll
        for (int c = 0; c < 64; c++) {
            const float4* kr = (const float4*)&Ksh[c][qd];
            float t0 = 0.f, t1 = 0.f, t2 = 0.f, t3 = 0.f;
#pragma unroll
            for (int ii = 0; ii < 4; ii++) {
                float4 kk = kr[ii];
                t0 += qreg[ii * 4 + 0] * kk.x;
                t1 += qreg[ii * 4 + 1] * kk.y;
                t2 += qreg[ii * 4 + 2] * kk.z;
                t3 += qreg[ii * 4 + 3] * kk.w;
            }
            s[c] = (t0 + t1) + (t2 + t3);
        }
        // Reduce across the 4 lanes of this row's quarter-warp
#pragma unroll
        for (int c = 0; c < 64; c++) {
            s[c] += __shfl_xor_sync(0xffffffffu, s[c], 1);
            s[c] += __shfl_xor_sync(0xffffffffu, s[c], 2);
        }

        float bm = s[0];
#pragma unroll
        for (int c = 1; c < 64; c++) bm = fmaxf(bm, s[c]);
        const float mnew = fmaxf(mrun, bm);
        const float corr = __expf(mrun - mnew);
        lsum *= corr;
#pragma unroll
        for (int i = 0; i < 16; i++) acc[i] *= corr;

#pragma unroll
        for (int c = 0; c < 64; c++) {
            const float p = __expf(s[c] - mnew);
            lsum += p;
            const float4* vr = (const float4*)&Vsh[c][qd];
#pragma unroll
            for (int ii = 0; ii < 4; ii++) {
                float4 vv = vr[ii];
                acc[ii * 4 + 0] += p * vv.x;
                acc[ii * 4 + 1] += p * vv.y;
                acc[ii * 4 + 2] += p * vv.z;
                acc[ii * 4 + 3] += p * vv.w;
            }
        }
        mrun = mnew;
    }

    // Write [B,S,D] with D index = h*DK + dk  (un-transposes heads)
    const float inv = 1.0f / lsum;
    const int b = bh >> 4;
    const int h = bh & 15;
    float* op = g_att + ((size_t)(b * Sc + row)) * Dc + h * DKc + qd;
#pragma unroll
    for (int i = 0; i < 16; i += 4) {
        float4 o;
        o.x = acc[i + 0] * inv;
        o.y = acc[i + 1] * inv;
        o.z = acc[i + 2] * inv;
        o.w = acc[i + 3] * inv;
        *(float4*)(op + i) = o;
    }
}

// ---------------------------------------------------------------------------
// Inputs (metadata order): q,k,v,mask,Wq,bq,Wk,bk,Wv,bv,Wo,bo
// mask is mathematically inert in the reference (preserved behavior).
// ---------------------------------------------------------------------------
extern "C" void kernel_launch(void* const* d_in, const int* in_sizes, int n_in,
                              void* d_out, int out_size) {
    (void)in_sizes; (void)n_in; (void)out_size;
    const float* q  = (const float*)d_in[0];
    const float* k  = (const float*)d_in[1];
    const float* v  = (const float*)d_in[2];
    const float* Wq = (const float*)d_in[4];
    const float* bq = (const float*)d_in[5];
    const float* Wk = (const float*)d_in[6];
    const float* bk = (const float*)d_in[7];
    const float* Wv = (const float*)d_in[8];
    const float* bv = (const float*)d_in[9];
    const float* Wo = (const float*)d_in[10];
    const float* bo = (const float*)d_in[11];
    float* out = (float*)d_out;

    dim3 gproj(Dc / 64, (Bc * Sc) / 64, 3);      // 16 x 64 x 3
    qkv_gemm_kernel<<<gproj, 256>>>(q, k, v, Wq, bq, Wk, bk, Wv, bv);

    dim3 gattn(Sc / 64, Bc * Hc);                // 32 x 32
    attn_kernel<<<gattn, 256>>>();

    dim3 gout(Dc / 64, (Bc * Sc) / 64);          // 16 x 64
    out_gemm_kernel<<<gout, 256>>>(Wo, bo, out);
}

// round 2
// speedup vs baseline: 2.4056x; 2.4056x over previous
#include <cuda_runtime.h>

constexpr int Bc  = 2;
constexpr int Sc  = 2048;
constexpr int Dc  = 1024;
constexpr int Hc  = 16;
constexpr int DKc = 64;

// Scratch (device globals: allocation-free per harness rules)
__device__ float g_qT[(size_t)Bc * Hc * DKc * Sc];  // [b,h,dk,s]  (transposed)
__device__ float g_kT[(size_t)Bc * Hc * DKc * Sc];  // [b,h,dk,s]  (transposed)
__device__ float g_v [(size_t)Bc * Hc * Sc * DKc];  // [b,h,s,dk]
__device__ float g_att[(size_t)Bc * Sc * Dc];       // [b,s,d]

// ---------------------------------------------------------------------------
// GEMM: C = A[4096,1024] @ W[1024,1024] + bias
// 128x128 tile, BK=16, 256 threads, 8x8 micro-tile, register prefetch.
// MODE 0: C[m][n] row-major. MODE 1: head-major transposed [b,h,dk,s].
// MODE 2: head-major [b,h,s,dk].
// ---------------------------------------------------------------------------
template <int MODE>
__device__ __forceinline__ void gemm_body(const float* __restrict__ A,
                                          const float* __restrict__ W,
                                          const float* __restrict__ bias,
                                          float* __restrict__ C) {
    __shared__ float As[16][128];   // [k][m]
    __shared__ float Bs[16][128];   // [k][n]

    const int tid = threadIdx.x;
    const int tx  = tid & 15;           // 16 threads across N
    const int ty  = tid >> 4;           // 16 threads across M
    const int m0  = blockIdx.y << 7;
    const int n0  = blockIdx.x << 7;

    // A-load mapping: rows am, am+64; k-quad ak (coalesced 64B per row)
    const int am = tid >> 2;            // 0..63
    const int ak = (tid & 3) << 2;      // 0,4,8,12
    // B-load mapping: row bk, 8 cols at bn
    const int bk = tid >> 4;            // 0..15
    const int bn = (tid & 15) << 3;     // 0..120

    const float* aptr0 = A + (size_t)(m0 + am) * Dc + ak;
    const float* aptr1 = A + (size_t)(m0 + am + 64) * Dc + ak;
    const float* bptr  = W + (size_t)bk * Dc + n0 + bn;

    float acc[8][8];
#pragma unroll
    for (int i = 0; i < 8; i++)
#pragma unroll
        for (int j = 0; j < 8; j++) acc[i][j] = 0.0f;

    // Prologue prefetch (iteration 0)
    float4 pa0 = *(const float4*)aptr0;
    float4 pa1 = *(const float4*)aptr1;
    float4 pb0 = *(const float4*)bptr;
    float4 pb1 = *(const float4*)(bptr + 4);

    const int NIT = Dc / 16;            // 64
    for (int it = 0; it < NIT; ++it) {
        // Commit prefetched tile to smem
        As[ak + 0][am]      = pa0.x;
        As[ak + 1][am]      = pa0.y;
        As[ak + 2][am]      = pa0.z;
        As[ak + 3][am]      = pa0.w;
        As[ak + 0][am + 64] = pa1.x;
        As[ak + 1][am + 64] = pa1.y;
        As[ak + 2][am + 64] = pa1.z;
        As[ak + 3][am + 64] = pa1.w;
        *(float4*)&Bs[bk][bn]     = pb0;
        *(float4*)&Bs[bk][bn + 4] = pb1;
        __syncthreads();

        // Prefetch next tile into registers (latency hidden by FFMA loop)
        if (it + 1 < NIT) {
            const int koff = (it + 1) << 4;
            pa0 = *(const float4*)(aptr0 + koff);
            pa1 = *(const float4*)(aptr1 + koff);
            pb0 = *(const float4*)(bptr + (size_t)koff * Dc);
            pb1 = *(const float4*)(bptr + (size_t)koff * Dc + 4);
        }

#pragma unroll
        for (int kk = 0; kk < 16; ++kk) {
            float4 a0 = *(const float4*)&As[kk][ty << 3];
            float4 a1 = *(const float4*)&As[kk][(ty << 3) + 4];
            float a[8] = {a0.x, a0.y, a0.z, a0.w, a1.x, a1.y, a1.z, a1.w};
            float b[8];
#pragma unroll
            for (int jj = 0; jj < 8; jj++) b[jj] = Bs[kk][tx + (jj << 4)];
#pragma unroll
            for (int ii = 0; ii < 8; ii++)
#pragma unroll
                for (int jj = 0; jj < 8; jj++) acc[ii][jj] += a[ii] * b[jj];
        }
        __syncthreads();
    }

    // Epilogue
    float bv[8];
#pragma unroll
    for (int jj = 0; jj < 8; jj++) bv[jj] = bias[n0 + tx + (jj << 4)];

#pragma unroll
    for (int ii = 0; ii < 8; ii++) {
        const int m = m0 + (ty << 3) + ii;
#pragma unroll
        for (int jj = 0; jj < 8; jj++) {
            const int n = n0 + tx + (jj << 4);
            const float val = acc[ii][jj] + bv[jj];
            if (MODE == 0) {
                C[(size_t)m * Dc + n] = val;
            } else {
                const int b  = m >> 11;          // m / S
                const int s  = m & (Sc - 1);     // m % S
                const int h  = n >> 6;           // n / DK
                const int dk = n & 63;           // n % DK
                if (MODE == 1)
                    C[(((size_t)(b * Hc + h)) * DKc + dk) * Sc + s] = val;
                else
                    C[(((size_t)(b * Hc + h)) * Sc + s) * DKc + dk] = val;
            }
        }
    }
}

__global__ __launch_bounds__(256, 2) void qkv_gemm_kernel(
    const float* __restrict__ q, const float* __restrict__ k, const float* __restrict__ v,
    const float* __restrict__ Wq, const float* __restrict__ biasq,
    const float* __restrict__ Wk, const float* __restrict__ biask,
    const float* __restrict__ Wv, const float* __restrict__ biasv) {
    if (blockIdx.z == 0)      gemm_body<1>(q, Wq, biasq, g_qT);
    else if (blockIdx.z == 1) gemm_body<1>(k, Wk, biask, g_kT);
    else                      gemm_body<2>(v, Wv, biasv, g_v);
}

__global__ __launch_bounds__(256, 2) void out_gemm_kernel(
    const float* __restrict__ Wo, const float* __restrict__ bo,
    float* __restrict__ out) {
    gemm_body<0>(g_att, Wo, bo, out);
}

// ---------------------------------------------------------------------------
// Flash attention as two register-tiled GEMMs.
// CTA: 128 threads; q-tile 64 rows; k-blocks of 64.
// Thread grid 16(tx) x 8(ty): S micro-tile = 8 rows x 4 cols (cols tx+16*jj),
// O micro-tile = 8 rows x 4 dk (dk = tx+16*jj). P staged via XOR-swizzled smem.
// ---------------------------------------------------------------------------
__global__ __launch_bounds__(128, 3) void attn_kernel() {
    __shared__ float Qs[64][64];   // [dk][qrow]   (from g_qT, pre-scaled)
    __shared__ float KV[64][64];   // K phase: [dk][krow]; V phase: [krow][dk]
    __shared__ float Ps[64][64];   // [krow][qrow ^ (krow&31)]

    const int tid = threadIdx.x;
    const int tx  = tid & 15;
    const int ty  = tid >> 4;
    const int bh  = blockIdx.y;            // b*H + h
    const int q0  = blockIdx.x << 6;

    // Load Q tile (transposed layout), pre-scaled by 1/sqrt(DK)=0.125
    const size_t qtBase = (size_t)bh * DKc * Sc + q0;
    for (int idx = tid; idx < 64 * 16; idx += 128) {
        const int d  = idx >> 4;
        const int c4 = (idx & 15) << 2;
        float4 t = *(const float4*)&g_qT[qtBase + (size_t)d * Sc + c4];
        t.x *= 0.125f; t.y *= 0.125f; t.z *= 0.125f; t.w *= 0.125f;
        *(float4*)&Qs[d][c4] = t;
    }

    float m[8], l[8], acc[8][4];
#pragma unroll
    for (int i = 0; i < 8; i++) {
        m[i] = -1e30f; l[i] = 0.0f;
#pragma unroll
        for (int j = 0; j < 4; j++) acc[i][j] = 0.0f;
    }

    const size_t ktBase = (size_t)bh * DKc * Sc;
    const size_t vBase  = (size_t)bh * Sc * DKc;

    for (int kb = 0; kb < Sc; kb += 64) {
        __syncthreads();   // prior O-gemm reads of KV/Ps complete

        // Load K block (transposed layout: [dk][krow]) — coalesced, conflict-free
        for (int idx = tid; idx < 64 * 16; idx += 128) {
            const int d  = idx >> 4;
            const int c4 = (idx & 15) << 2;
            *(float4*)&KV[d][c4] =
                *(const float4*)&g_kT[ktBase + (size_t)d * Sc + kb + c4];
        }
        __syncthreads();

        // S = Q @ K^T  (inner dim dk)
        float s[8][4];
#pragma unroll
        for (int ii = 0; ii < 8; ii++)
#pragma unroll
            for (int jj = 0; jj < 4; jj++) s[ii][jj] = 0.0f;

#pragma unroll 8
        for (int d = 0; d < 64; ++d) {
            float4 a0 = *(const float4*)&Qs[d][ty << 3];
            float4 a1 = *(const float4*)&Qs[d][(ty << 3) + 4];
            float a[8] = {a0.x, a0.y, a0.z, a0.w, a1.x, a1.y, a1.z, a1.w};
            float b[4];
#pragma unroll
            for (int jj = 0; jj < 4; jj++) b[jj] = KV[d][tx + (jj << 4)];
#pragma unroll
            for (int ii = 0; ii < 8; ii++)
#pragma unroll
                for (int jj = 0; jj < 4; jj++) s[ii][jj] += a[ii] * b[jj];
        }
        __syncthreads();   // S-gemm reads of KV done → safe to overwrite with V

        // Online softmax (registers + 16-lane shfl reductions)
#pragma unroll
        for (int ii = 0; ii < 8; ii++) {
            float rm = fmaxf(fmaxf(s[ii][0], s[ii][1]), fmaxf(s[ii][2], s[ii][3]));
            rm = fmaxf(rm, __shfl_xor_sync(0xffffffffu, rm, 1));
            rm = fmaxf(rm, __shfl_xor_sync(0xffffffffu, rm, 2));
            rm = fmaxf(rm, __shfl_xor_sync(0xffffffffu, rm, 4));
            rm = fmaxf(rm, __shfl_xor_sync(0xffffffffu, rm, 8));
            const float mn   = fmaxf(m[ii], rm);
            const float corr = __expf(m[ii] - mn);
            m[ii] = mn;
            float rs = 0.0f;
#pragma unroll
            for (int jj = 0; jj < 4; jj++) {
                const float p = __expf(s[ii][jj] - mn);
                s[ii][jj] = p;
                rs += p;
            }
            rs += __shfl_xor_sync(0xffffffffu, rs, 1);
            rs += __shfl_xor_sync(0xffffffffu, rs, 2);
            rs += __shfl_xor_sync(0xffffffffu, rs, 4);
            rs += __shfl_xor_sync(0xffffffffu, rs, 8);
            l[ii] = l[ii] * corr + rs;
#pragma unroll
            for (int jj = 0; jj < 4; jj++) acc[ii][jj] *= corr;
        }

        // Store P swizzled: Ps[j][i ^ (j&31)] — conflict-free stores
#pragma unroll
        for (int jj = 0; jj < 4; jj++) {
            const int j  = tx + (jj << 4);
            const int sw = j & 31;
#pragma unroll
            for (int ii = 0; ii < 8; ii++)
                Ps[j][((ty << 3) + ii) ^ sw] = s[ii][jj];
        }

        // Load V block natural layout [krow][dk]
        for (int idx = tid; idx < 64 * 16; idx += 128) {
            const int r  = idx >> 4;
            const int c4 = (idx & 15) << 2;
            *(float4*)&KV[r][c4] =
                *(const float4*)&g_v[vBase + (size_t)(kb + r) * DKc + c4];
        }
        __syncthreads();

        // O += P @ V  (inner dim krow)
#pragma unroll 8
        for (int j = 0; j < 64; ++j) {
            const int sw = j & 31;
            float ap[8];
#pragma unroll
            for (int ii = 0; ii < 8; ii++) ap[ii] = Ps[j][((ty << 3) + ii) ^ sw];
            float bv4[4];
#pragma unroll
            for (int jj = 0; jj < 4; jj++) bv4[jj] = KV[j][tx + (jj << 4)];
#pragma unroll
            for (int ii = 0; ii < 8; ii++)
#pragma unroll
                for (int jj = 0; jj < 4; jj++) acc[ii][jj] += ap[ii] * bv4[jj];
        }
    }

    // Write O into [b,s,d] (un-transpose heads); coalesced 4B x 16-lane runs
    const int b = bh >> 4;
    const int h = bh & 15;
#pragma unroll
    for (int ii = 0; ii < 8; ii++) {
        const float inv = 1.0f / l[ii];
        const int row = q0 + (ty << 3) + ii;
        float* op = g_att + (size_t)(b * Sc + row) * Dc + h * DKc + tx;
#pragma unroll
        for (int jj = 0; jj < 4; jj++) op[jj << 4] = acc[ii][jj] * inv;
    }
}

// ---------------------------------------------------------------------------
// Inputs (metadata order): q,k,v,mask,Wq,bq,Wk,bk,Wv,bv,Wo,bo
// mask is mathematically inert in the reference (preserved behavior).
// ---------------------------------------------------------------------------
extern "C" void kernel_launch(void* const* d_in, const int* in_sizes, int n_in,
                              void* d_out, int out_size) {
    (void)in_sizes; (void)n_in; (void)out_size;
    const float* q  = (const float*)d_in[0];
    const float* k  = (const float*)d_in[1];
    const float* v  = (const float*)d_in[2];
    const float* Wq = (const float*)d_in[4];
    const float* bq = (const float*)d_in[5];
    const float* Wk = (const float*)d_in[6];
    const float* bk = (const float*)d_in[7];
    const float* Wv = (const float*)d_in[8];
    const float* bv = (const float*)d_in[9];
    const float* Wo = (const float*)d_in[10];
    const float* bo = (const float*)d_in[11];
    float* out = (float*)d_out;

    dim3 gproj(Dc / 128, (Bc * Sc) / 128, 3);    // 8 x 32 x 3
    qkv_gemm_kernel<<<gproj, 256>>>(q, k, v, Wq, bq, Wk, bk, Wv, bv);

    dim3 gattn(Sc / 64, Bc * Hc);                // 32 x 32
    attn_kernel<<<gattn, 128>>>();

    dim3 gout(Dc / 128, (Bc * Sc) / 128);        // 8 x 32
    out_gemm_kernel<<<gout, 256>>>(Wo, bo, out);
}